// round 12
// baseline (speedup 1.0000x reference)
#include <cuda_runtime.h>
#include <stdint.h>
#include <math.h>

// Per-block partial sums (written unconditionally every call -> no zeroing needed).
__device__ double g_part_lcc[512][3];
__device__ double g_part_aux[444][2];
__device__ unsigned int g_count = 0;  // self-resetting arrival counter

#define TOTAL_BLOCKS 1024u

__device__ __forceinline__ float warp_redf(float v) {
#pragma unroll
    for (int o = 16; o > 0; o >>= 1) v += __shfl_down_sync(0xffffffffu, v, o);
    return v;
}
__device__ __forceinline__ double warp_redd(double v) {
#pragma unroll
    for (int o = 16; o > 0; o >>= 1) v += __shfl_down_sync(0xffffffffu, v, o);
    return v;
}

// 16-byte cp.async with zero-fill when srcsize==0
__device__ __forceinline__ void cp16(unsigned int dst, const float* src, int srcsize) {
    asm volatile("cp.async.cg.shared.global [%0], [%1], 16, %2;"
                 :: "r"(dst), "l"(src), "r"(srcsize) : "memory");
}
#define CP_COMMIT() asm volatile("cp.async.commit_group;" ::: "memory")
#define CP_WAIT2()  asm volatile("cp.async.wait_group 2;" ::: "memory")

#define TW 32
#define TH 16
#define SW 40       // padded smem row: w0-4 .. w0+35 (16B aligned slots)
#define HH 20       // TH + 4 halo
#define SLICE (HH * SW)   // 800 floats
#define DEPTH 4
#define NOPS 400    // cp ops: 20 rows * 10 slots * 2 arrays

// ---------------------------------------------------------------------------
// Mega kernel. Even blockIdx.x -> LCC tile (vectorized cp.async-pipelined
// 5x5x5 box-mean + reduction, ONE barrier per z-slice, vectorized tap-shared
// row stage), odd -> streaming aux. Last block reduces partials.
// ---------------------------------------------------------------------------
__global__ __launch_bounds__(512, 2) void mega_kernel(
    const float* __restrict__ F0, const float* __restrict__ F0g,
    const float* __restrict__ I0, const float* __restrict__ I0R,
    const float* __restrict__ I1, const float* __restrict__ I1R,
    const float* __restrict__ S0, const float* __restrict__ S0g,
    const float* __restrict__ S1, const float* __restrict__ S1g,
    float* __restrict__ out)
{
    __shared__ float bufA[DEPTH][SLICE];   // 12800 B
    __shared__ float bufB[DEPTH][SLICE];   // 12800 B
    __shared__ float rA[2][HH][TW];        // 5120 B
    __shared__ float rB[2][HH][TW];        // 5120 B
    __shared__ float redf[16][3];
    __shared__ double redd[16][2];
    __shared__ unsigned s_last;

    const int b = blockIdx.x;
    const int tid = threadIdx.x;
    const int lane = tid & 31, wid = tid >> 5;

    if (b & 1) {
        // ---------------- aux path: streaming reductions ----------------
        const int ab = b >> 1;
        if (ab < 444) {
            int task, abl, nblk;
            if (ab < 264)      { task = 0; abl = ab;       nblk = 264; }
            else if (ab < 354) { task = 1; abl = ab - 264; nblk = 90;  }
            else               { task = 2; abl = ab - 354; nblk = 90;  }
            const int gid = abl * 512 + tid;
            const int stride = nblk * 512;

            float f0 = 0.f, f1 = 0.f;
            if (task == 0) {
                const float4* __restrict__ a = (const float4*)F0;
                const float4* __restrict__ c = (const float4*)F0g;
                const int n4 = 12582912 / 4;
#pragma unroll 4
                for (int i = gid; i < n4; i += stride) {
                    const float4 va = a[i], vb = c[i];
                    const float d0 = vb.x - va.x, d1 = vb.y - va.y;
                    const float d2 = vb.z - va.z, d3 = vb.w - va.w;
                    f0 += (d0 * d0 + d1 * d1) + (d2 * d2 + d3 * d3);
                }
            } else {
                const float4* __restrict__ a = (const float4*)(task == 1 ? S0 : S1);
                const float4* __restrict__ c = (const float4*)(task == 1 ? S0g : S1g);
                const int n4 = 4194304 / 4;
#pragma unroll 4
                for (int i = gid; i < n4; i += stride) {
                    const float4 va = a[i], vb = c[i];
                    f0 += ((va.x + vb.x) + (va.y + vb.y)) + ((va.z + vb.z) + (va.w + vb.w));
                    f1 += (va.x * vb.x + va.y * vb.y) + (va.z * vb.z + va.w * vb.w);
                }
            }
            double s0 = (double)f0, s1 = (double)f1;
            s0 = warp_redd(s0); s1 = warp_redd(s1);
            if (lane == 0) { redd[wid][0] = s0; redd[wid][1] = s1; }
            __syncthreads();
            if (wid == 0) {
                double v0 = (lane < 16) ? redd[lane][0] : 0.0;
                double v1 = (lane < 16) ? redd[lane][1] : 0.0;
                v0 = warp_redd(v0); v1 = warp_redd(v1);
                if (lane == 0) { g_part_aux[ab][0] = v0; g_part_aux[ab][1] = v1; }
            }
        }
    } else {
        // ---------------- LCC path ----------------
        const int lb = b >> 1;                 // 0..511
        const int tile = lb & 127;
        const int bi = lb >> 7;                // pair*2 + batch
        const int batch = bi & 1;
        const int pair = bi >> 1;

        const float* __restrict__ gt = pair ? I1 : I0;
        const float* __restrict__ pr = pair ? I1R : I0R;

        const int wt = tile & 3;
        const int ht = (tile >> 2) & 7;
        const int ck = tile >> 5;
        const int w0 = wt * TW, h0 = ht * TH, d0 = ck * 32;
        const long base = (long)batch * (128L * 128L * 128L);

        const int tx = tid & 31, ty = tid >> 5;

        // --- per-thread vector load slot: one 16B cp.async per slice ---
        const bool hasop = (tid < NOPS);
        const int o = hasop ? tid : 0;
        const int arr = (o >= 200) ? 1 : 0;
        const int j = o - arr * 200;
        const int rr = j / 10, q = j - rr * 10;
        const int gh = h0 + rr - 2;
        const int gw4 = w0 - 4 + q * 4;
        const bool pvalid = hasop && ((unsigned)gh < 128u) && ((unsigned)gw4 <= 124u);
        const long po = base + (pvalid ? ((long)gh * 128 + gw4) : 0L);
        const float* const srcbase = arr ? pr : gt;

        const unsigned int aB = (unsigned int)__cvta_generic_to_shared(&bufA[0][0]);
        const unsigned int bB = (unsigned int)__cvta_generic_to_shared(&bufB[0][0]);
        const unsigned int dst0 = (arr ? bB : aB) + (unsigned int)(rr * SW + q * 4) * 4u;

        // --- row-stage task: 320 threads, 4-wide output groups ---
        // warps 0..4 -> array A, warps 5..9 -> array B (warp-uniform)
        const bool rowact = (tid < 320);
        const int rarr = (tid >= 160) ? 1 : 0;
        const int rj = (rowact ? tid : 0) - rarr * 160;
        const int rrr = rj >> 3, rq = rj & 7;         // row 0..19, group 0..7
        const int rsrc = rrr * SW + rq * 4;           // float idx of f0 within slice
        const int rdst = 0;                            // (computed inline)

        // rings + center delay + accumulators
        float qA0 = 0, qA1 = 0, qA2 = 0, qA3 = 0, qA4 = 0;
        float qB0 = 0, qB1 = 0, qB2 = 0, qB3 = 0, qB4 = 0;
        float cA0 = 0, cA1 = 0, cA2 = 0;
        float cB0 = 0, cB1 = 0, cB2 = 0;
        float aN = 0.f, aG = 0.f, aP = 0.f;

        auto issue_slice = [&](int d, int k) {
            if (hasop) {
                const int dcl = d < 0 ? 0 : (d > 127 ? 127 : d);
                const bool dv = ((unsigned)d < 128u);
                const int sz = (dv && pvalid) ? 16 : 0;
                cp16(dst0 + (unsigned int)k * (SLICE * 4u), srcbase + po + (long)dcl * 16384, sz);
            }
        };

        issue_slice(d0 - 2, 0); CP_COMMIT();
        issue_slice(d0 - 1, 1); CP_COMMIT();
        issue_slice(d0,     2); CP_COMMIT();

        const int ci = (ty + 2) * SW + (tx + 4);  // center slot for this thread

#pragma unroll 4
        for (int it = 0; it < 36; ++it) {
            CP_WAIT2();            // this thread's copies for slice `it` done
            __syncthreads();       // everyone's copies landed; prev readers done
            if (it < 33) issue_slice(d0 + 1 + it, (it + 3) & 3);
            CP_COMMIT();           // commit every iteration (keeps group count aligned)

            // --- col stage for slice it-1 (reads rA[(it-1)&1]) ---
            if (it >= 1) {
                const int pp = (it - 1) & 1;
                const float nA = ((rA[pp][ty][tx] + rA[pp][ty + 1][tx]) +
                                  (rA[pp][ty + 2][tx] + rA[pp][ty + 3][tx])) + rA[pp][ty + 4][tx];
                const float nB = ((rB[pp][ty][tx] + rB[pp][ty + 1][tx]) +
                                  (rB[pp][ty + 2][tx] + rB[pp][ty + 3][tx])) + rB[pp][ty + 4][tx];
                qA0 = qA1; qA1 = qA2; qA2 = qA3; qA3 = qA4; qA4 = nA;
                qB0 = qB1; qB1 = qB2; qB2 = qB3; qB3 = qB4; qB4 = nB;
                if (it - 1 >= 4) {
                    const float zA = ((qA0 + qA1) + (qA2 + qA3)) + qA4;
                    const float zB = ((qB0 + qB1) + (qB2 + qB3)) + qB4;
                    const float dA = fmaf(zA, -(1.0f / 125.0f), cA2);
                    const float dB = fmaf(zB, -(1.0f / 125.0f), cB2);
                    aN = fmaf(dA, dB, aN);
                    aG = fmaf(dA, dA, aG);
                    aP = fmaf(dB, dB, aP);
                }
            }

            // --- row stage for slice `it`: vectorized 4-wide tap-shared ---
            {
                const int k = it & 3, pp = it & 1;
                if (rowact) {
                    const float* __restrict__ src = (rarr ? bufB[k] : bufA[k]) + rsrc;
                    const float4 v0 = *(const float4*)(src);
                    const float4 v1 = *(const float4*)(src + 4);
                    const float4 v2 = *(const float4*)(src + 8);
                    // f0..f11 = v0.xyzw v1.xyzw v2.xyzw ; outputs k=0..3:
                    // outk = f[k+2]+f[k+3]+f[k+4]+f[k+5]+f[k+6]
                    const float a34 = v0.w + v1.x;            // f3+f4
                    const float m2  = v1.y + v1.z;            // f5+f6
                    const float m   = a34 + m2;               // f3..f6
                    const float p78 = v1.w + v2.x;            // f7+f8
                    float4 r;
                    r.x = v0.z + m;                           // f2 + (f3..f6)
                    r.y = m + v1.w;                           // (f3..f6) + f7
                    r.z = (v1.x + m2) + p78;                  // f4+f5+f6+f7+f8
                    r.w = (m2 + p78) + v2.y;                  // f5+f6+f7+f8+f9
                    float* __restrict__ dstp = (rarr ? &rB[pp][rrr][rq * 4]
                                                     : &rA[pp][rrr][rq * 4]);
                    *(float4*)dstp = r;
                }
                // center delay line (all threads, own output)
                const float* __restrict__ sa = bufA[k];
                const float* __restrict__ sb = bufB[k];
                cA2 = cA1; cA1 = cA0; cA0 = sa[ci];
                cB2 = cB1; cB1 = cB0; cB0 = sb[ci];
            }
        }
        // epilogue: col stage for slice 35 (rA[1] written at it=35)
        __syncthreads();
        {
            const float nA = ((rA[1][ty][tx] + rA[1][ty + 1][tx]) +
                              (rA[1][ty + 2][tx] + rA[1][ty + 3][tx])) + rA[1][ty + 4][tx];
            const float nB = ((rB[1][ty][tx] + rB[1][ty + 1][tx]) +
                              (rB[1][ty + 2][tx] + rB[1][ty + 3][tx])) + rB[1][ty + 4][tx];
            qA0 = qA1; qA1 = qA2; qA2 = qA3; qA3 = qA4; qA4 = nA;
            qB0 = qB1; qB1 = qB2; qB2 = qB3; qB3 = qB4; qB4 = nB;
            const float zA = ((qA0 + qA1) + (qA2 + qA3)) + qA4;
            const float zB = ((qB0 + qB1) + (qB2 + qB3)) + qB4;
            const float dA = fmaf(zA, -(1.0f / 125.0f), cA2);
            const float dB = fmaf(zB, -(1.0f / 125.0f), cB2);
            aN = fmaf(dA, dB, aN);
            aG = fmaf(dA, dA, aG);
            aP = fmaf(dB, dB, aP);
        }

        aN = warp_redf(aN); aG = warp_redf(aG); aP = warp_redf(aP);
        if (lane == 0) { redf[wid][0] = aN; redf[wid][1] = aG; redf[wid][2] = aP; }
        __syncthreads();
        if (wid == 0) {
            float vN = (lane < 16) ? redf[lane][0] : 0.f;
            float vG = (lane < 16) ? redf[lane][1] : 0.f;
            float vP = (lane < 16) ? redf[lane][2] : 0.f;
            vN = warp_redf(vN); vG = warp_redf(vG); vP = warp_redf(vP);
            if (lane == 0) {
                g_part_lcc[lb][0] = (double)vN;
                g_part_lcc[lb][1] = (double)vG;
                g_part_lcc[lb][2] = (double)vP;
            }
        }
    }

    // ---------------- arrival + last-block finalization ----------------
    __syncthreads();
    if (tid == 0) {
        __threadfence();
        const unsigned old = atomicAdd(&g_count, 1u);
        const unsigned last = (old == TOTAL_BLOCKS - 1u);
        s_last = last;
        if (last) g_count = 0u;  // self-reset for next graph replay
    }
    __syncthreads();
    if (!s_last) return;

    __shared__ double facc[11];
    if (tid < 11) facc[tid] = 0.0;
    __syncthreads();
    {
        double vN = g_part_lcc[tid][0];
        double vG = g_part_lcc[tid][1];
        double vP = g_part_lcc[tid][2];
        const int pair = tid >> 8;  // warp-uniform
        vN = warp_redd(vN); vG = warp_redd(vG); vP = warp_redd(vP);
        if (lane == 0) {
            atomicAdd(&facc[1 + 3 * pair], vN);
            atomicAdd(&facc[2 + 3 * pair], vG);
            atomicAdd(&facc[3 + 3 * pair], vP);
        }
    }
    if (tid < 444) {
        const int task = (tid < 264) ? 0 : (tid < 354 ? 1 : 2);
        const double v0 = g_part_aux[tid][0];
        const double v1 = g_part_aux[tid][1];
        if (task == 0) {
            atomicAdd(&facc[0], v0);
        } else {
            atomicAdd(&facc[7 + 2 * (task - 1)], v0);
            atomicAdd(&facc[8 + 2 * (task - 1)], v1);
        }
    }
    __syncthreads();
    if (tid == 0) {
        double r = sqrt(facc[0]) / 12582912.0;  // reg_field_loss
#pragma unroll
        for (int k = 0; k < 2; ++k) {
            double num = facc[1 + 3 * k];
            num *= num;
            double den = facc[2 + 3 * k] * facc[3 + 3 * k];
            den = den > 1e-5 ? den : 1e-5;
            r += 10.0 * (-(num / den) / 4194304.0);  // lcc
            double ta = facc[7 + 2 * k];
            ta = ta > 1e-5 ? ta : 1e-5;
            r += 10.0 * (-(facc[8 + 2 * k] / ta));   // tversky
        }
        out[0] = (float)r;
    }
}

extern "C" void kernel_launch(void* const* d_in, const int* in_sizes, int n_in,
                              void* d_out, int out_size) {
    const float* F0  = (const float*)d_in[0];
    const float* F0g = (const float*)d_in[1];
    const float* I0  = (const float*)d_in[2];
    const float* I0R = (const float*)d_in[3];
    const float* I1  = (const float*)d_in[4];
    const float* I1R = (const float*)d_in[5];
    const float* S0  = (const float*)d_in[6];
    const float* S0g = (const float*)d_in[7];
    const float* S1  = (const float*)d_in[8];
    const float* S1g = (const float*)d_in[9];

    mega_kernel<<<TOTAL_BLOCKS, 512>>>(F0, F0g, I0, I0R, I1, I1R,
                                       S0, S0g, S1, S1g, (float*)d_out);
}

// round 13
// speedup vs baseline: 1.1390x; 1.1390x over previous
#include <cuda_runtime.h>
#include <stdint.h>
#include <math.h>

// Per-block partial sums (written unconditionally every call -> no zeroing needed).
__device__ double g_part_lcc[128][3];
__device__ double g_part_aux[176][2];
__device__ unsigned int g_count = 0;  // self-resetting arrival counter

#define TOTAL_BLOCKS 304u   // 152 SMs * 2 : bids 0..127 LCC, 128..303 aux

__device__ __forceinline__ float warp_redf(float v) {
#pragma unroll
    for (int o = 16; o > 0; o >>= 1) v += __shfl_down_sync(0xffffffffu, v, o);
    return v;
}
__device__ __forceinline__ double warp_redd(double v) {
#pragma unroll
    for (int o = 16; o > 0; o >>= 1) v += __shfl_down_sync(0xffffffffu, v, o);
    return v;
}

// 16-byte cp.async with zero-fill when srcsize==0
__device__ __forceinline__ void cp16(unsigned int dst, const float* src, int srcsize) {
    asm volatile("cp.async.cg.shared.global [%0], [%1], 16, %2;"
                 :: "r"(dst), "l"(src), "r"(srcsize) : "memory");
}
#define CP_COMMIT() asm volatile("cp.async.commit_group;" ::: "memory")
#define CP_WAIT2()  asm volatile("cp.async.wait_group 2;" ::: "memory")

#define TW 32
#define TH 16
#define SW 40       // padded smem row: w0-4 .. w0+35 (16B aligned slots)
#define HH 20       // TH + 4 halo
#define SLICE (HH * SW)   // 800 floats
#define DEPTH 4
#define NOPS 400    // cp ops: 20 rows * 10 slots * 2 arrays
#define N_IT 132    // full-depth sweep: loads d = -2 .. 129

// ---------------------------------------------------------------------------
// Mega kernel, single wave. bid < 128 -> LCC full-depth column (cp.async-
// pipelined 5x5x5 box-mean + reduction, one barrier per z-slice);
// bid >= 128 -> streaming aux. Last block reduces partials, writes scalar.
// ---------------------------------------------------------------------------
__global__ __launch_bounds__(512, 2) void mega_kernel(
    const float* __restrict__ F0, const float* __restrict__ F0g,
    const float* __restrict__ I0, const float* __restrict__ I0R,
    const float* __restrict__ I1, const float* __restrict__ I1R,
    const float* __restrict__ S0, const float* __restrict__ S0g,
    const float* __restrict__ S1, const float* __restrict__ S1g,
    float* __restrict__ out)
{
    __shared__ float bufA[DEPTH][SLICE];   // 12800 B
    __shared__ float bufB[DEPTH][SLICE];   // 12800 B
    __shared__ float rA[2][HH][TW];        // 5120 B
    __shared__ float rB[2][HH][TW];        // 5120 B
    __shared__ float redf[16][3];
    __shared__ double redd[16][2];
    __shared__ unsigned s_last;

    const int b = blockIdx.x;
    const int tid = threadIdx.x;
    const int lane = tid & 31, wid = tid >> 5;

    if (b >= 128) {
        // ---------------- aux path: streaming reductions ----------------
        const int ab = b - 128;               // 0..175
        int task, abl, nblk;
        if (ab < 106)      { task = 0; abl = ab;       nblk = 106; }
        else if (ab < 141) { task = 1; abl = ab - 106; nblk = 35;  }
        else               { task = 2; abl = ab - 141; nblk = 35;  }
        const int gid = abl * 512 + tid;
        const int stride = nblk * 512;

        float f0 = 0.f, f1 = 0.f;
        if (task == 0) {
            const float4* __restrict__ a = (const float4*)F0;
            const float4* __restrict__ c = (const float4*)F0g;
            const int n4 = 12582912 / 4;
#pragma unroll 4
            for (int i = gid; i < n4; i += stride) {
                const float4 va = a[i], vb = c[i];
                const float d0 = vb.x - va.x, d1 = vb.y - va.y;
                const float d2 = vb.z - va.z, d3 = vb.w - va.w;
                f0 += (d0 * d0 + d1 * d1) + (d2 * d2 + d3 * d3);
            }
        } else {
            const float4* __restrict__ a = (const float4*)(task == 1 ? S0 : S1);
            const float4* __restrict__ c = (const float4*)(task == 1 ? S0g : S1g);
            const int n4 = 4194304 / 4;
#pragma unroll 4
            for (int i = gid; i < n4; i += stride) {
                const float4 va = a[i], vb = c[i];
                f0 += ((va.x + vb.x) + (va.y + vb.y)) + ((va.z + vb.z) + (va.w + vb.w));
                f1 += (va.x * vb.x + va.y * vb.y) + (va.z * vb.z + va.w * vb.w);
            }
        }
        double s0 = (double)f0, s1 = (double)f1;
        s0 = warp_redd(s0); s1 = warp_redd(s1);
        if (lane == 0) { redd[wid][0] = s0; redd[wid][1] = s1; }
        __syncthreads();
        if (wid == 0) {
            double v0 = (lane < 16) ? redd[lane][0] : 0.0;
            double v1 = (lane < 16) ? redd[lane][1] : 0.0;
            v0 = warp_redd(v0); v1 = warp_redd(v1);
            if (lane == 0) { g_part_aux[ab][0] = v0; g_part_aux[ab][1] = v1; }
        }
    } else {
        // ---------------- LCC path: full-depth column ----------------
        const int lb = b;                      // 0..127
        const int tile = lb & 31;              // 4w * 8h
        const int bi = lb >> 5;                // pair*2 + batch
        const int batch = bi & 1;
        const int pair = bi >> 1;

        const float* __restrict__ gt = pair ? I1 : I0;
        const float* __restrict__ pr = pair ? I1R : I0R;

        const int wt = tile & 3;
        const int ht = tile >> 2;              // 0..7
        const int w0 = wt * TW, h0 = ht * TH;
        const long base = (long)batch * (128L * 128L * 128L);

        const int tx = tid & 31, ty = tid >> 5;

        // --- per-thread vector load slot: one 16B cp.async per slice ---
        const bool hasop = (tid < NOPS);
        const int o = hasop ? tid : 0;
        const int arr = (o >= 200) ? 1 : 0;
        const int j = o - arr * 200;
        const int rr = j / 10, q = j - rr * 10;
        const int gh = h0 + rr - 2;
        const int gw4 = w0 - 4 + q * 4;
        const bool pvalid = hasop && ((unsigned)gh < 128u) && ((unsigned)gw4 <= 124u);
        const long po = base + (pvalid ? ((long)gh * 128 + gw4) : 0L);
        const float* const srcbase = arr ? pr : gt;

        const unsigned int aB = (unsigned int)__cvta_generic_to_shared(&bufA[0][0]);
        const unsigned int bB = (unsigned int)__cvta_generic_to_shared(&bufB[0][0]);
        const unsigned int dst0 = (arr ? bB : aB) + (unsigned int)(rr * SW + q * 4) * 4u;

        // rings + center delay + accumulators
        float qA0 = 0, qA1 = 0, qA2 = 0, qA3 = 0, qA4 = 0;
        float qB0 = 0, qB1 = 0, qB2 = 0, qB3 = 0, qB4 = 0;
        float cA0 = 0, cA1 = 0, cA2 = 0;
        float cB0 = 0, cB1 = 0, cB2 = 0;
        float aN = 0.f, aG = 0.f, aP = 0.f;

        // issue this thread's copy for slice d (abs), into ring buffer k
        auto issue_slice = [&](int d, int k) {
            if (hasop) {
                const int dcl = d < 0 ? 0 : (d > 127 ? 127 : d);
                const bool dv = ((unsigned)d < 128u);
                const int sz = (dv && pvalid) ? 16 : 0;
                cp16(dst0 + (unsigned int)k * (SLICE * 4u), srcbase + po + (long)dcl * 16384, sz);
            }
        };

        // prologue: slices d = -2, -1, 0 into rings 0,1,2
        issue_slice(-2, 0); CP_COMMIT();
        issue_slice(-1, 1); CP_COMMIT();
        issue_slice( 0, 2); CP_COMMIT();

        const int ci = (ty + 2) * SW + (tx + 4);  // center slot for this thread

        for (int it = 0; it < N_IT; ++it) {
            CP_WAIT2();            // this thread's copies for slice `it` done
            __syncthreads();       // everyone's copies landed; prev readers done
            if (it < N_IT - 3) issue_slice(1 + it, (it + 3) & 3);
            CP_COMMIT();           // commit every iteration (keeps group count aligned)

            // --- col stage for slice it-1 (reads rA[(it-1)&1]) ---
            if (it >= 1) {
                const int pp = (it - 1) & 1;
                const float nA = ((rA[pp][ty][tx] + rA[pp][ty + 1][tx]) +
                                  (rA[pp][ty + 2][tx] + rA[pp][ty + 3][tx])) + rA[pp][ty + 4][tx];
                const float nB = ((rB[pp][ty][tx] + rB[pp][ty + 1][tx]) +
                                  (rB[pp][ty + 2][tx] + rB[pp][ty + 3][tx])) + rB[pp][ty + 4][tx];
                qA0 = qA1; qA1 = qA2; qA2 = qA3; qA3 = qA4; qA4 = nA;
                qB0 = qB1; qB1 = qB2; qB2 = qB3; qB3 = qB4; qB4 = nB;
                if (it - 1 >= 4) {
                    const float zA = ((qA0 + qA1) + (qA2 + qA3)) + qA4;
                    const float zB = ((qB0 + qB1) + (qB2 + qB3)) + qB4;
                    const float dA = fmaf(zA, -(1.0f / 125.0f), cA2);
                    const float dB = fmaf(zB, -(1.0f / 125.0f), cB2);
                    aN = fmaf(dA, dB, aN);
                    aG = fmaf(dA, dA, aG);
                    aP = fmaf(dB, dB, aP);
                }
            }

            // --- row stage for slice `it` (writes rA[it&1], pushes center) ---
            {
                const int k = it & 3, pp = it & 1;
                const float* __restrict__ sa = bufA[k];
                const float* __restrict__ sb = bufB[k];
#pragma unroll 2
                for (int i = tid; i < HH * TW; i += 512) {
                    const int hh = i >> 5, w = i & 31;
                    const int oo = hh * SW + w + 2;   // padded start w0-4; output center +4
                    rA[pp][hh][w] = ((sa[oo] + sa[oo + 1]) + (sa[oo + 2] + sa[oo + 3])) + sa[oo + 4];
                    rB[pp][hh][w] = ((sb[oo] + sb[oo + 1]) + (sb[oo + 2] + sb[oo + 3])) + sb[oo + 4];
                }
                cA2 = cA1; cA1 = cA0; cA0 = sa[ci];
                cB2 = cB1; cB1 = cB0; cB0 = sb[ci];
            }
        }
        // epilogue: col stage for slice N_IT-1 (rA[(N_IT-1)&1] = rA[1])
        __syncthreads();
        {
            const float nA = ((rA[1][ty][tx] + rA[1][ty + 1][tx]) +
                              (rA[1][ty + 2][tx] + rA[1][ty + 3][tx])) + rA[1][ty + 4][tx];
            const float nB = ((rB[1][ty][tx] + rB[1][ty + 1][tx]) +
                              (rB[1][ty + 2][tx] + rB[1][ty + 3][tx])) + rB[1][ty + 4][tx];
            qA0 = qA1; qA1 = qA2; qA2 = qA3; qA3 = qA4; qA4 = nA;
            qB0 = qB1; qB1 = qB2; qB2 = qB3; qB3 = qB4; qB4 = nB;
            const float zA = ((qA0 + qA1) + (qA2 + qA3)) + qA4;
            const float zB = ((qB0 + qB1) + (qB2 + qB3)) + qB4;
            const float dA = fmaf(zA, -(1.0f / 125.0f), cA2);
            const float dB = fmaf(zB, -(1.0f / 125.0f), cB2);
            aN = fmaf(dA, dB, aN);
            aG = fmaf(dA, dA, aG);
            aP = fmaf(dB, dB, aP);
        }

        aN = warp_redf(aN); aG = warp_redf(aG); aP = warp_redf(aP);
        if (lane == 0) { redf[wid][0] = aN; redf[wid][1] = aG; redf[wid][2] = aP; }
        __syncthreads();
        if (wid == 0) {
            float vN = (lane < 16) ? redf[lane][0] : 0.f;
            float vG = (lane < 16) ? redf[lane][1] : 0.f;
            float vP = (lane < 16) ? redf[lane][2] : 0.f;
            vN = warp_redf(vN); vG = warp_redf(vG); vP = warp_redf(vP);
            if (lane == 0) {
                g_part_lcc[lb][0] = (double)vN;
                g_part_lcc[lb][1] = (double)vG;
                g_part_lcc[lb][2] = (double)vP;
            }
        }
    }

    // ---------------- arrival + last-block finalization ----------------
    __syncthreads();
    if (tid == 0) {
        __threadfence();
        const unsigned old = atomicAdd(&g_count, 1u);
        const unsigned last = (old == TOTAL_BLOCKS - 1u);
        s_last = last;
        if (last) g_count = 0u;  // self-reset for next graph replay
    }
    __syncthreads();
    if (!s_last) return;

    __shared__ double facc[11];
    if (tid < 11) facc[tid] = 0.0;
    __syncthreads();
    if (tid < 128) {
        double vN = g_part_lcc[tid][0];
        double vG = g_part_lcc[tid][1];
        double vP = g_part_lcc[tid][2];
        const int pair = tid >> 6;  // 0..1, warp-uniform (64-aligned)
        vN = warp_redd(vN); vG = warp_redd(vG); vP = warp_redd(vP);
        if (lane == 0) {
            atomicAdd(&facc[1 + 3 * pair], vN);
            atomicAdd(&facc[2 + 3 * pair], vG);
            atomicAdd(&facc[3 + 3 * pair], vP);
        }
    }
    if (tid < 176) {
        const int task = (tid < 106) ? 0 : (tid < 141 ? 1 : 2);
        const double v0 = g_part_aux[tid][0];
        const double v1 = g_part_aux[tid][1];
        if (task == 0) {
            atomicAdd(&facc[0], v0);
        } else {
            atomicAdd(&facc[7 + 2 * (task - 1)], v0);
            atomicAdd(&facc[8 + 2 * (task - 1)], v1);
        }
    }
    __syncthreads();
    if (tid == 0) {
        double r = sqrt(facc[0]) / 12582912.0;  // reg_field_loss
#pragma unroll
        for (int k = 0; k < 2; ++k) {
            double num = facc[1 + 3 * k];
            num *= num;
            double den = facc[2 + 3 * k] * facc[3 + 3 * k];
            den = den > 1e-5 ? den : 1e-5;
            r += 10.0 * (-(num / den) / 4194304.0);  // lcc
            double ta = facc[7 + 2 * k];
            ta = ta > 1e-5 ? ta : 1e-5;
            r += 10.0 * (-(facc[8 + 2 * k] / ta));   // tversky
        }
        out[0] = (float)r;
    }
}

extern "C" void kernel_launch(void* const* d_in, const int* in_sizes, int n_in,
                              void* d_out, int out_size) {
    const float* F0  = (const float*)d_in[0];
    const float* F0g = (const float*)d_in[1];
    const float* I0  = (const float*)d_in[2];
    const float* I0R = (const float*)d_in[3];
    const float* I1  = (const float*)d_in[4];
    const float* I1R = (const float*)d_in[5];
    const float* S0  = (const float*)d_in[6];
    const float* S0g = (const float*)d_in[7];
    const float* S1  = (const float*)d_in[8];
    const float* S1g = (const float*)d_in[9];

    mega_kernel<<<TOTAL_BLOCKS, 512>>>(F0, F0g, I0, I0R, I1, I1R,
                                       S0, S0g, S1, S1g, (float*)d_out);
}

// round 14
// speedup vs baseline: 1.5200x; 1.3345x over previous
#include <cuda_runtime.h>
#include <stdint.h>
#include <math.h>

// Per-block partial sums (written unconditionally every call -> no zeroing needed).
__device__ double g_part_lcc[512][3];
__device__ double g_part_aux[444][2];
__device__ unsigned int g_count = 0;  // self-resetting arrival counter

#define TOTAL_BLOCKS 1024u

__device__ __forceinline__ float warp_redf(float v) {
#pragma unroll
    for (int o = 16; o > 0; o >>= 1) v += __shfl_down_sync(0xffffffffu, v, o);
    return v;
}
__device__ __forceinline__ double warp_redd(double v) {
#pragma unroll
    for (int o = 16; o > 0; o >>= 1) v += __shfl_down_sync(0xffffffffu, v, o);
    return v;
}

// 16-byte cp.async with zero-fill when srcsize==0
__device__ __forceinline__ void cp16(unsigned int dst, const float* src, int srcsize) {
    asm volatile("cp.async.cg.shared.global [%0], [%1], 16, %2;"
                 :: "r"(dst), "l"(src), "r"(srcsize) : "memory");
}
#define CP_COMMIT() asm volatile("cp.async.commit_group;" ::: "memory")
#define CP_WAIT2()  asm volatile("cp.async.wait_group 2;" ::: "memory")

#define TW 32
#define TH 16
#define SW 40       // padded smem row: w0-4 .. w0+35 (16B aligned slots)
#define HH 20       // TH + 4 halo
#define SLICE (HH * SW)   // 800 floats
#define DEPTH 4
#define NOPS 400    // cp ops: 20 rows * 10 slots * 2 arrays

// ---------------------------------------------------------------------------
// Mega kernel. Even blockIdx.x -> LCC tile (cp.async-pipelined 5x5x5 box-mean
// + reduction, one barrier per z-slice, statically-unrolled ring indices,
// float2 tap-shared row stage), odd -> streaming aux. Last block finalizes.
// ---------------------------------------------------------------------------
__global__ __launch_bounds__(512, 2) void mega_kernel(
    const float* __restrict__ F0, const float* __restrict__ F0g,
    const float* __restrict__ I0, const float* __restrict__ I0R,
    const float* __restrict__ I1, const float* __restrict__ I1R,
    const float* __restrict__ S0, const float* __restrict__ S0g,
    const float* __restrict__ S1, const float* __restrict__ S1g,
    float* __restrict__ out)
{
    __shared__ float bufA[DEPTH][SLICE];   // 12800 B
    __shared__ float bufB[DEPTH][SLICE];   // 12800 B
    __shared__ float rA[2][HH][TW];        // 5120 B
    __shared__ float rB[2][HH][TW];        // 5120 B
    __shared__ float redf[16][3];
    __shared__ double redd[16][2];
    __shared__ unsigned s_last;

    const int b = blockIdx.x;
    const int tid = threadIdx.x;
    const int lane = tid & 31, wid = tid >> 5;

    if (b & 1) {
        // ---------------- aux path: streaming reductions ----------------
        const int ab = b >> 1;
        if (ab < 444) {
            int task, abl, nblk;
            if (ab < 264)      { task = 0; abl = ab;       nblk = 264; }
            else if (ab < 354) { task = 1; abl = ab - 264; nblk = 90;  }
            else               { task = 2; abl = ab - 354; nblk = 90;  }
            const int gid = abl * 512 + tid;
            const int stride = nblk * 512;

            float f0 = 0.f, f1 = 0.f;
            if (task == 0) {
                const float4* __restrict__ a = (const float4*)F0;
                const float4* __restrict__ c = (const float4*)F0g;
                const int n4 = 12582912 / 4;
#pragma unroll 4
                for (int i = gid; i < n4; i += stride) {
                    const float4 va = a[i], vb = c[i];
                    const float d0 = vb.x - va.x, d1 = vb.y - va.y;
                    const float d2 = vb.z - va.z, d3 = vb.w - va.w;
                    f0 += (d0 * d0 + d1 * d1) + (d2 * d2 + d3 * d3);
                }
            } else {
                const float4* __restrict__ a = (const float4*)(task == 1 ? S0 : S1);
                const float4* __restrict__ c = (const float4*)(task == 1 ? S0g : S1g);
                const int n4 = 4194304 / 4;
#pragma unroll 4
                for (int i = gid; i < n4; i += stride) {
                    const float4 va = a[i], vb = c[i];
                    f0 += ((va.x + vb.x) + (va.y + vb.y)) + ((va.z + vb.z) + (va.w + vb.w));
                    f1 += (va.x * vb.x + va.y * vb.y) + (va.z * vb.z + va.w * vb.w);
                }
            }
            double s0 = (double)f0, s1 = (double)f1;
            s0 = warp_redd(s0); s1 = warp_redd(s1);
            if (lane == 0) { redd[wid][0] = s0; redd[wid][1] = s1; }
            __syncthreads();
            if (wid == 0) {
                double v0 = (lane < 16) ? redd[lane][0] : 0.0;
                double v1 = (lane < 16) ? redd[lane][1] : 0.0;
                v0 = warp_redd(v0); v1 = warp_redd(v1);
                if (lane == 0) { g_part_aux[ab][0] = v0; g_part_aux[ab][1] = v1; }
            }
        }
    } else {
        // ---------------- LCC path ----------------
        const int lb = b >> 1;                 // 0..511
        const int tile = lb & 127;
        const int bi = lb >> 7;                // pair*2 + batch
        const int batch = bi & 1;
        const int pair = bi >> 1;

        const float* __restrict__ gt = pair ? I1 : I0;
        const float* __restrict__ pr = pair ? I1R : I0R;

        const int wt = tile & 3;
        const int ht = (tile >> 2) & 7;
        const int ck = tile >> 5;
        const int w0 = wt * TW, h0 = ht * TH, d0 = ck * 32;
        const long base = (long)batch * (128L * 128L * 128L);

        const int tx = tid & 31, ty = tid >> 5;

        // --- per-thread vector load slot: one 16B cp.async per slice ---
        const bool hasop = (tid < NOPS);
        const int o = hasop ? tid : 0;
        const int arr = (o >= 200) ? 1 : 0;
        const int j = o - arr * 200;
        const int rr0 = j / 10, q = j - rr0 * 10;
        const int gh = h0 + rr0 - 2;
        const int gw4 = w0 - 4 + q * 4;
        const bool pvalid = hasop && ((unsigned)gh < 128u) && ((unsigned)gw4 <= 124u);
        const long po = base + (pvalid ? ((long)gh * 128 + gw4) : 0L);
        const float* const srcbase = arr ? pr : gt;

        const unsigned int aB = (unsigned int)__cvta_generic_to_shared(&bufA[0][0]);
        const unsigned int bB = (unsigned int)__cvta_generic_to_shared(&bufB[0][0]);
        const unsigned int dst0 = (arr ? bB : aB) + (unsigned int)(rr0 * SW + q * 4) * 4u;

        // --- paired row-stage task (320 threads): 2 outputs per array ---
        const bool rowact = (tid < 320);
        const int rr = (rowact ? tid : 0) >> 4;   // 0..19
        const int rp = tid & 15;                  // 0..15
        const int roff = rr * SW + rp * 2 + 2;    // even -> float2 aligned

        // rings + center delay + accumulators
        float qA0 = 0, qA1 = 0, qA2 = 0, qA3 = 0, qA4 = 0;
        float qB0 = 0, qB1 = 0, qB2 = 0, qB3 = 0, qB4 = 0;
        float cA0 = 0, cA1 = 0, cA2 = 0;
        float cB0 = 0, cB1 = 0, cB2 = 0;
        float aN = 0.f, aG = 0.f, aP = 0.f;

        auto issue_slice = [&](int d, int k) {
            if (hasop) {
                const int dcl = d < 0 ? 0 : (d > 127 ? 127 : d);
                const bool dv = ((unsigned)d < 128u);
                const int sz = (dv && pvalid) ? 16 : 0;
                cp16(dst0 + (unsigned int)k * (SLICE * 4u), srcbase + po + (long)dcl * 16384, sz);
            }
        };

        issue_slice(d0 - 2, 0); CP_COMMIT();
        issue_slice(d0 - 1, 1); CP_COMMIT();
        issue_slice(d0,     2); CP_COMMIT();

        const int ci = (ty + 2) * SW + (tx + 4);  // center slot for this thread

        for (int g = 0; g < 9; ++g) {
#pragma unroll
            for (int it_in = 0; it_in < 4; ++it_in) {
                const int it = g * 4 + it_in;       // it_in literal -> static k/pp
                CP_WAIT2();
                __syncthreads();
                if (it < 33) issue_slice(d0 + 1 + it, (it_in + 3) & 3);
                CP_COMMIT();

                // --- col stage for slice it-1 (reads rA[(it-1)&1]) ---
                if (it >= 1) {
                    const int pp = (it_in + 3) & 1;   // (it-1)&1, static
                    const float nA = ((rA[pp][ty][tx] + rA[pp][ty + 1][tx]) +
                                      (rA[pp][ty + 2][tx] + rA[pp][ty + 3][tx])) + rA[pp][ty + 4][tx];
                    const float nB = ((rB[pp][ty][tx] + rB[pp][ty + 1][tx]) +
                                      (rB[pp][ty + 2][tx] + rB[pp][ty + 3][tx])) + rB[pp][ty + 4][tx];
                    qA0 = qA1; qA1 = qA2; qA2 = qA3; qA3 = qA4; qA4 = nA;
                    qB0 = qB1; qB1 = qB2; qB2 = qB3; qB3 = qB4; qB4 = nB;
                    if (it >= 5) {                    // slice it-1 >= 4 -> emit
                        const float zA = ((qA0 + qA1) + (qA2 + qA3)) + qA4;
                        const float zB = ((qB0 + qB1) + (qB2 + qB3)) + qB4;
                        const float dA = fmaf(zA, -(1.0f / 125.0f), cA2);
                        const float dB = fmaf(zB, -(1.0f / 125.0f), cB2);
                        aN = fmaf(dA, dB, aN);
                        aG = fmaf(dA, dA, aG);
                        aP = fmaf(dB, dB, aP);
                    }
                }

                // --- row stage for slice it: float2 tap-shared pairs ---
                {
                    const int k = it_in, pp = it_in & 1;   // static
                    if (rowact) {
                        const float2* pa = (const float2*)(bufA[k] + roff);
                        const float2 a0 = pa[0], a1 = pa[1], a2 = pa[2];
                        const float mA = (a0.y + a1.x) + (a1.y + a2.x);
                        float2 ra; ra.x = a0.x + mA; ra.y = mA + a2.y;
                        *(float2*)&rA[pp][rr][rp * 2] = ra;

                        const float2* pb = (const float2*)(bufB[k] + roff);
                        const float2 b0 = pb[0], b1 = pb[1], b2 = pb[2];
                        const float mB = (b0.y + b1.x) + (b1.y + b2.x);
                        float2 rb; rb.x = b0.x + mB; rb.y = mB + b2.y;
                        *(float2*)&rB[pp][rr][rp * 2] = rb;
                    }
                    // center delay line (all threads)
                    cA2 = cA1; cA1 = cA0; cA0 = bufA[k][ci];
                    cB2 = cB1; cB1 = cB0; cB0 = bufB[k][ci];
                }
            }
        }
        // epilogue: col stage for slice 35 (rA[1], written at it=35)
        __syncthreads();
        {
            const float nA = ((rA[1][ty][tx] + rA[1][ty + 1][tx]) +
                              (rA[1][ty + 2][tx] + rA[1][ty + 3][tx])) + rA[1][ty + 4][tx];
            const float nB = ((rB[1][ty][tx] + rB[1][ty + 1][tx]) +
                              (rB[1][ty + 2][tx] + rB[1][ty + 3][tx])) + rB[1][ty + 4][tx];
            qA0 = qA1; qA1 = qA2; qA2 = qA3; qA3 = qA4; qA4 = nA;
            qB0 = qB1; qB1 = qB2; qB2 = qB3; qB3 = qB4; qB4 = nB;
            const float zA = ((qA0 + qA1) + (qA2 + qA3)) + qA4;
            const float zB = ((qB0 + qB1) + (qB2 + qB3)) + qB4;
            const float dA = fmaf(zA, -(1.0f / 125.0f), cA2);
            const float dB = fmaf(zB, -(1.0f / 125.0f), cB2);
            aN = fmaf(dA, dB, aN);
            aG = fmaf(dA, dA, aG);
            aP = fmaf(dB, dB, aP);
        }

        aN = warp_redf(aN); aG = warp_redf(aG); aP = warp_redf(aP);
        if (lane == 0) { redf[wid][0] = aN; redf[wid][1] = aG; redf[wid][2] = aP; }
        __syncthreads();
        if (wid == 0) {
            float vN = (lane < 16) ? redf[lane][0] : 0.f;
            float vG = (lane < 16) ? redf[lane][1] : 0.f;
            float vP = (lane < 16) ? redf[lane][2] : 0.f;
            vN = warp_redf(vN); vG = warp_redf(vG); vP = warp_redf(vP);
            if (lane == 0) {
                g_part_lcc[lb][0] = (double)vN;
                g_part_lcc[lb][1] = (double)vG;
                g_part_lcc[lb][2] = (double)vP;
            }
        }
    }

    // ---------------- arrival + last-block finalization ----------------
    __syncthreads();
    if (tid == 0) {
        __threadfence();
        const unsigned old = atomicAdd(&g_count, 1u);
        const unsigned last = (old == TOTAL_BLOCKS - 1u);
        s_last = last;
        if (last) g_count = 0u;  // self-reset for next graph replay
    }
    __syncthreads();
    if (!s_last) return;

    __shared__ double facc[11];
    if (tid < 11) facc[tid] = 0.0;
    __syncthreads();
    {
        double vN = g_part_lcc[tid][0];
        double vG = g_part_lcc[tid][1];
        double vP = g_part_lcc[tid][2];
        const int pair = tid >> 8;  // warp-uniform
        vN = warp_redd(vN); vG = warp_redd(vG); vP = warp_redd(vP);
        if (lane == 0) {
            atomicAdd(&facc[1 + 3 * pair], vN);
            atomicAdd(&facc[2 + 3 * pair], vG);
            atomicAdd(&facc[3 + 3 * pair], vP);
        }
    }
    if (tid < 444) {
        const int task = (tid < 264) ? 0 : (tid < 354 ? 1 : 2);
        const double v0 = g_part_aux[tid][0];
        const double v1 = g_part_aux[tid][1];
        if (task == 0) {
            atomicAdd(&facc[0], v0);
        } else {
            atomicAdd(&facc[7 + 2 * (task - 1)], v0);
            atomicAdd(&facc[8 + 2 * (task - 1)], v1);
        }
    }
    __syncthreads();
    if (tid == 0) {
        double r = sqrt(facc[0]) / 12582912.0;  // reg_field_loss
#pragma unroll
        for (int k = 0; k < 2; ++k) {
            double num = facc[1 + 3 * k];
            num *= num;
            double den = facc[2 + 3 * k] * facc[3 + 3 * k];
            den = den > 1e-5 ? den : 1e-5;
            r += 10.0 * (-(num / den) / 4194304.0);  // lcc
            double ta = facc[7 + 2 * k];
            ta = ta > 1e-5 ? ta : 1e-5;
            r += 10.0 * (-(facc[8 + 2 * k] / ta));   // tversky
        }
        out[0] = (float)r;
    }
}

extern "C" void kernel_launch(void* const* d_in, const int* in_sizes, int n_in,
                              void* d_out, int out_size) {
    const float* F0  = (const float*)d_in[0];
    const float* F0g = (const float*)d_in[1];
    const float* I0  = (const float*)d_in[2];
    const float* I0R = (const float*)d_in[3];
    const float* I1  = (const float*)d_in[4];
    const float* I1R = (const float*)d_in[5];
    const float* S0  = (const float*)d_in[6];
    const float* S0g = (const float*)d_in[7];
    const float* S1  = (const float*)d_in[8];
    const float* S1g = (const float*)d_in[9];

    mega_kernel<<<TOTAL_BLOCKS, 512>>>(F0, F0g, I0, I0R, I1, I1R,
                                       S0, S0g, S1, S1g, (float*)d_out);
}

// round 16
// speedup vs baseline: 1.7310x; 1.1388x over previous
#include <cuda_runtime.h>
#include <stdint.h>
#include <math.h>

// Per-block partial sums (written unconditionally every call -> no zeroing needed).
__device__ double g_part_lcc[512][3];
__device__ double g_part_aux[512][5];   // reg_sumsq, tv0_sum, tv0_dot, tv1_sum, tv1_dot
__device__ unsigned int g_count = 0;    // self-resetting arrival counter

#define TOTAL_BLOCKS 512u

// aux unit space: one unit = one float4 index into a (src,ref) array pair
#define REG_N4 3145728   // 12582912/4
#define T0_END 4194304   // REG_N4 + 1048576
#define T1_END 5242880   // + 1048576
#define UNITS_PER_BLOCK 10240   // T1_END / 512
#define AUX_ITERS 20            // 10240 / 512 threads

__device__ __forceinline__ float warp_redf(float v) {
#pragma unroll
    for (int o = 16; o > 0; o >>= 1) v += __shfl_down_sync(0xffffffffu, v, o);
    return v;
}
__device__ __forceinline__ double warp_redd(double v) {
#pragma unroll
    for (int o = 16; o > 0; o >>= 1) v += __shfl_down_sync(0xffffffffu, v, o);
    return v;
}

// 16-byte cp.async with zero-fill when srcsize==0
__device__ __forceinline__ void cp16(unsigned int dst, const float* src, int srcsize) {
    asm volatile("cp.async.cg.shared.global [%0], [%1], 16, %2;"
                 :: "r"(dst), "l"(src), "r"(srcsize) : "memory");
}
#define CP_COMMIT() asm volatile("cp.async.commit_group;" ::: "memory")
#define CP_WAIT2()  asm volatile("cp.async.wait_group 2;" ::: "memory")

#define TW 32
#define TH 16
#define SW 40       // padded smem row: w0-4 .. w0+35 (16B aligned slots)
#define HH 20       // TH + 4 halo
#define SLICE (HH * SW)   // 800 floats
#define DEPTH 4
#define NOPS 400    // cp ops: 20 rows * 10 slots * 2 arrays

// ---------------------------------------------------------------------------
// Fused kernel: every block runs one LCC tile (cp.async-pipelined 5x5x5
// box-mean + reduction, one barrier per z-slice, static ring indices) AND
// streams its 1/512 share of the reg/tversky reductions during iterations
// 0..19 (loads at top of iteration, accumulate at bottom -> latency hidden
// behind the stencil stages). Last block reduces partials, writes scalar.
// ---------------------------------------------------------------------------
__global__ __launch_bounds__(512, 2) void mega_kernel(
    const float* __restrict__ F0, const float* __restrict__ F0g,
    const float* __restrict__ I0, const float* __restrict__ I0R,
    const float* __restrict__ I1, const float* __restrict__ I1R,
    const float* __restrict__ S0, const float* __restrict__ S0g,
    const float* __restrict__ S1, const float* __restrict__ S1g,
    float* __restrict__ out)
{
    __shared__ float bufA[DEPTH][SLICE];   // 12800 B
    __shared__ float bufB[DEPTH][SLICE];   // 12800 B
    __shared__ float rA[2][HH][TW];        // 5120 B
    __shared__ float rB[2][HH][TW];        // 5120 B
    __shared__ float redf[16][8];
    __shared__ unsigned s_last;

    const int b = blockIdx.x;
    const int tid = threadIdx.x;
    const int lane = tid & 31, wid = tid >> 5;

    // ---------------- LCC tile decode (identical to R14) ----------------
    const int lb = b;                      // 0..511
    const int tile = lb & 127;
    const int bi = lb >> 7;                // pair*2 + batch
    const int batch = bi & 1;
    const int pair = bi >> 1;

    const float* __restrict__ gt = pair ? I1 : I0;
    const float* __restrict__ pr = pair ? I1R : I0R;

    const int wt = tile & 3;
    const int ht = (tile >> 2) & 7;
    const int ck = tile >> 5;
    const int w0 = wt * TW, h0 = ht * TH, d0 = ck * 32;
    const long base = (long)batch * (128L * 128L * 128L);

    const int tx = tid & 31, ty = tid >> 5;

    // --- per-thread vector load slot: one 16B cp.async per slice ---
    const bool hasop = (tid < NOPS);
    const int o = hasop ? tid : 0;
    const int arr = (o >= 200) ? 1 : 0;
    const int j = o - arr * 200;
    const int rr0 = j / 10, q = j - rr0 * 10;
    const int gh = h0 + rr0 - 2;
    const int gw4 = w0 - 4 + q * 4;
    const bool pvalid = hasop && ((unsigned)gh < 128u) && ((unsigned)gw4 <= 124u);
    const long po = base + (pvalid ? ((long)gh * 128 + gw4) : 0L);
    const float* const srcbase = arr ? pr : gt;

    const unsigned int aB = (unsigned int)__cvta_generic_to_shared(&bufA[0][0]);
    const unsigned int bB = (unsigned int)__cvta_generic_to_shared(&bufB[0][0]);
    const unsigned int dst0 = (arr ? bB : aB) + (unsigned int)(rr0 * SW + q * 4) * 4u;

    // --- paired row-stage task (320 threads): 2 outputs per array ---
    const bool rowact = (tid < 320);
    const int rr = (rowact ? tid : 0) >> 4;   // 0..19
    const int rp = tid & 15;                  // 0..15
    const int roff = rr * SW + rp * 2 + 2;    // even -> float2 aligned

    // --- aux share: base unit for this block ---
    const int aux_base = b * UNITS_PER_BLOCK;

    // rings + center delay + accumulators
    float qA0 = 0, qA1 = 0, qA2 = 0, qA3 = 0, qA4 = 0;
    float qB0 = 0, qB1 = 0, qB2 = 0, qB3 = 0, qB4 = 0;
    float cA0 = 0, cA1 = 0, cA2 = 0;
    float cB0 = 0, cB1 = 0, cB2 = 0;
    float aN = 0.f, aG = 0.f, aP = 0.f;
    float accR = 0.f, t0s = 0.f, t0d = 0.f, t1s = 0.f, t1d = 0.f;

    auto issue_slice = [&](int d, int k) {
        if (hasop) {
            const int dcl = d < 0 ? 0 : (d > 127 ? 127 : d);
            const bool dv = ((unsigned)d < 128u);
            const int sz = (dv && pvalid) ? 16 : 0;
            cp16(dst0 + (unsigned int)k * (SLICE * 4u), srcbase + po + (long)dcl * 16384, sz);
        }
    };

    issue_slice(d0 - 2, 0); CP_COMMIT();
    issue_slice(d0 - 1, 1); CP_COMMIT();
    issue_slice(d0,     2); CP_COMMIT();

    const int ci = (ty + 2) * SW + (tx + 4);  // center slot for this thread

    for (int g = 0; g < 9; ++g) {
#pragma unroll
        for (int it_in = 0; it_in < 4; ++it_in) {
            const int it = g * 4 + it_in;       // it_in literal -> static k/pp
            CP_WAIT2();
            __syncthreads();
            if (it < 33) issue_slice(d0 + 1 + it, (it_in + 3) & 3);
            CP_COMMIT();

            // --- aux load phase (iterations 0..19): issue two independent
            //     LDG.128 now, accumulate at the bottom of the iteration ---
            float4 xva, xvb;
            int tkind = 3;                       // 3 = inactive
            if (it < AUX_ITERS) {
                const int u = aux_base + it * 512 + tid;   // < 5242880
                const float* pa; const float* pc; int i4;
                if (u < REG_N4)      { pa = F0; pc = F0g; i4 = u;           tkind = 0; }
                else if (u < T0_END) { pa = S0; pc = S0g; i4 = u - REG_N4;  tkind = 1; }
                else                 { pa = S1; pc = S1g; i4 = u - T0_END;  tkind = 2; }
                xva = ((const float4*)pa)[i4];
                xvb = ((const float4*)pc)[i4];
            }

            // --- col stage for slice it-1 (reads rA[(it-1)&1]) ---
            if (it >= 1) {
                const int pp = (it_in + 3) & 1;   // (it-1)&1, static
                const float nA = ((rA[pp][ty][tx] + rA[pp][ty + 1][tx]) +
                                  (rA[pp][ty + 2][tx] + rA[pp][ty + 3][tx])) + rA[pp][ty + 4][tx];
                const float nB = ((rB[pp][ty][tx] + rB[pp][ty + 1][tx]) +
                                  (rB[pp][ty + 2][tx] + rB[pp][ty + 3][tx])) + rB[pp][ty + 4][tx];
                qA0 = qA1; qA1 = qA2; qA2 = qA3; qA3 = qA4; qA4 = nA;
                qB0 = qB1; qB1 = qB2; qB2 = qB3; qB3 = qB4; qB4 = nB;
                if (it >= 5) {                    // slice it-1 >= 4 -> emit
                    const float zA = ((qA0 + qA1) + (qA2 + qA3)) + qA4;
                    const float zB = ((qB0 + qB1) + (qB2 + qB3)) + qB4;
                    const float dA = fmaf(zA, -(1.0f / 125.0f), cA2);
                    const float dB = fmaf(zB, -(1.0f / 125.0f), cB2);
                    aN = fmaf(dA, dB, aN);
                    aG = fmaf(dA, dA, aG);
                    aP = fmaf(dB, dB, aP);
                }
            }

            // --- row stage for slice it: float2 tap-shared pairs ---
            {
                const int k = it_in, pp = it_in & 1;   // static
                if (rowact) {
                    const float2* pa2 = (const float2*)(bufA[k] + roff);
                    const float2 a0 = pa2[0], a1 = pa2[1], a2 = pa2[2];
                    const float mA = (a0.y + a1.x) + (a1.y + a2.x);
                    float2 ra; ra.x = a0.x + mA; ra.y = mA + a2.y;
                    *(float2*)&rA[pp][rr][rp * 2] = ra;

                    const float2* pb2 = (const float2*)(bufB[k] + roff);
                    const float2 b0 = pb2[0], b1 = pb2[1], b2 = pb2[2];
                    const float mB = (b0.y + b1.x) + (b1.y + b2.x);
                    float2 rb; rb.x = b0.x + mB; rb.y = mB + b2.y;
                    *(float2*)&rB[pp][rr][rp * 2] = rb;
                }
                // center delay line (all threads)
                cA2 = cA1; cA1 = cA0; cA0 = bufA[k][ci];
                cB2 = cB1; cB1 = cB0; cB0 = bufB[k][ci];
            }

            // --- aux accumulate phase (loads have had a full iteration) ---
            if (tkind == 0) {
                const float d0f = xvb.x - xva.x, d1f = xvb.y - xva.y;
                const float d2f = xvb.z - xva.z, d3f = xvb.w - xva.w;
                accR += (d0f * d0f + d1f * d1f) + (d2f * d2f + d3f * d3f);
            } else if (tkind < 3) {
                const float s = ((xva.x + xvb.x) + (xva.y + xvb.y)) +
                                ((xva.z + xvb.z) + (xva.w + xvb.w));
                const float d = (xva.x * xvb.x + xva.y * xvb.y) +
                                (xva.z * xvb.z + xva.w * xvb.w);
                if (tkind == 1) { t0s += s; t0d += d; }
                else            { t1s += s; t1d += d; }
            }
        }
    }
    // epilogue: col stage for slice 35 (rA[1], written at it=35)
    __syncthreads();
    {
        const float nA = ((rA[1][ty][tx] + rA[1][ty + 1][tx]) +
                          (rA[1][ty + 2][tx] + rA[1][ty + 3][tx])) + rA[1][ty + 4][tx];
        const float nB = ((rB[1][ty][tx] + rB[1][ty + 1][tx]) +
                          (rB[1][ty + 2][tx] + rB[1][ty + 3][tx])) + rB[1][ty + 4][tx];
        qA0 = qA1; qA1 = qA2; qA2 = qA3; qA3 = qA4; qA4 = nA;
        qB0 = qB1; qB1 = qB2; qB2 = qB3; qB3 = qB4; qB4 = nB;
        const float zA = ((qA0 + qA1) + (qA2 + qA3)) + qA4;
        const float zB = ((qB0 + qB1) + (qB2 + qB3)) + qB4;
        const float dA = fmaf(zA, -(1.0f / 125.0f), cA2);
        const float dB = fmaf(zB, -(1.0f / 125.0f), cB2);
        aN = fmaf(dA, dB, aN);
        aG = fmaf(dA, dA, aG);
        aP = fmaf(dB, dB, aP);
    }

    // ---------------- block reduction of 8 partials ----------------
    float v0 = warp_redf(aN),  v1 = warp_redf(aG),  v2 = warp_redf(aP);
    float v3 = warp_redf(accR), v4 = warp_redf(t0s), v5 = warp_redf(t0d);
    float v6 = warp_redf(t1s),  v7 = warp_redf(t1d);
    if (lane == 0) {
        redf[wid][0] = v0; redf[wid][1] = v1; redf[wid][2] = v2; redf[wid][3] = v3;
        redf[wid][4] = v4; redf[wid][5] = v5; redf[wid][6] = v6; redf[wid][7] = v7;
    }
    __syncthreads();
    if (wid == 0) {
        float w0v = (lane < 16) ? redf[lane][0] : 0.f;
        float w1v = (lane < 16) ? redf[lane][1] : 0.f;
        float w2v = (lane < 16) ? redf[lane][2] : 0.f;
        float w3v = (lane < 16) ? redf[lane][3] : 0.f;
        float w4v = (lane < 16) ? redf[lane][4] : 0.f;
        float w5v = (lane < 16) ? redf[lane][5] : 0.f;
        float w6v = (lane < 16) ? redf[lane][6] : 0.f;
        float w7v = (lane < 16) ? redf[lane][7] : 0.f;
        w0v = warp_redf(w0v); w1v = warp_redf(w1v); w2v = warp_redf(w2v);
        w3v = warp_redf(w3v); w4v = warp_redf(w4v); w5v = warp_redf(w5v);
        w6v = warp_redf(w6v); w7v = warp_redf(w7v);
        if (lane == 0) {
            g_part_lcc[b][0] = (double)w0v;
            g_part_lcc[b][1] = (double)w1v;
            g_part_lcc[b][2] = (double)w2v;
            g_part_aux[b][0] = (double)w3v;
            g_part_aux[b][1] = (double)w4v;
            g_part_aux[b][2] = (double)w5v;
            g_part_aux[b][3] = (double)w6v;
            g_part_aux[b][4] = (double)w7v;
        }
    }

    // ---------------- arrival + last-block finalization ----------------
    __syncthreads();
    if (tid == 0) {
        __threadfence();
        const unsigned old = atomicAdd(&g_count, 1u);
        const unsigned last = (old == TOTAL_BLOCKS - 1u);
        s_last = last;
        if (last) g_count = 0u;  // self-reset for next graph replay
    }
    __syncthreads();
    if (!s_last) return;

    __shared__ double facc[11];
    if (tid < 11) facc[tid] = 0.0;
    __syncthreads();
    {
        double dN = g_part_lcc[tid][0];
        double dG = g_part_lcc[tid][1];
        double dP = g_part_lcc[tid][2];
        double a0 = g_part_aux[tid][0];
        double a1 = g_part_aux[tid][1];
        double a2 = g_part_aux[tid][2];
        double a3 = g_part_aux[tid][3];
        double a4 = g_part_aux[tid][4];
        const int pr2 = tid >> 8;  // warp-uniform (256-aligned)
        dN = warp_redd(dN); dG = warp_redd(dG); dP = warp_redd(dP);
        a0 = warp_redd(a0); a1 = warp_redd(a1); a2 = warp_redd(a2);
        a3 = warp_redd(a3); a4 = warp_redd(a4);
        if (lane == 0) {
            atomicAdd(&facc[1 + 3 * pr2], dN);
            atomicAdd(&facc[2 + 3 * pr2], dG);
            atomicAdd(&facc[3 + 3 * pr2], dP);
            atomicAdd(&facc[0], a0);
            atomicAdd(&facc[7], a1);
            atomicAdd(&facc[8], a2);
            atomicAdd(&facc[9], a3);
            atomicAdd(&facc[10], a4);
        }
    }
    __syncthreads();
    if (tid == 0) {
        double r = sqrt(facc[0]) / 12582912.0;  // reg_field_loss
#pragma unroll
        for (int k = 0; k < 2; ++k) {
            double num = facc[1 + 3 * k];
            num *= num;
            double den = facc[2 + 3 * k] * facc[3 + 3 * k];
            den = den > 1e-5 ? den : 1e-5;
            r += 10.0 * (-(num / den) / 4194304.0);  // lcc
            double ta = facc[7 + 2 * k];
            ta = ta > 1e-5 ? ta : 1e-5;
            r += 10.0 * (-(facc[8 + 2 * k] / ta));   // tversky
        }
        out[0] = (float)r;
    }
}

extern "C" void kernel_launch(void* const* d_in, const int* in_sizes, int n_in,
                              void* d_out, int out_size) {
    const float* F0  = (const float*)d_in[0];
    const float* F0g = (const float*)d_in[1];
    const float* I0  = (const float*)d_in[2];
    const float* I0R = (const float*)d_in[3];
    const float* I1  = (const float*)d_in[4];
    const float* I1R = (const float*)d_in[5];
    const float* S0  = (const float*)d_in[6];
    const float* S0g = (const float*)d_in[7];
    const float* S1  = (const float*)d_in[8];
    const float* S1g = (const float*)d_in[9];

    mega_kernel<<<TOTAL_BLOCKS, 512>>>(F0, F0g, I0, I0R, I1, I1R,
                                       S0, S0g, S1, S1g, (float*)d_out);
}